// round 2
// baseline (speedup 1.0000x reference)
#include <cuda_runtime.h>
#include <cuda_bf16.h>
#include <math.h>

#define BB 32
#define CC 2048
#define HH 48
#define WW 24
#define PP 3
#define PHH 16
#define HD 8
#define WD 12
#define NN 96
#define ICC 128
#define C4 512
#define BN (BB*NN)   // 3072

// ---------------- scratch (device globals; no allocations allowed) ----------------
__device__ float g_xd[(size_t)PP*CC*BB*NN];     // (p,c,b,n)
__device__ float g_xmean[(size_t)PP*CC*BB];     // (p,c,b)
__device__ float g_wqk[(size_t)PP*256*CC];      // effective QK weights
__device__ float g_bqk[PP*256];
__device__ float g_qk[(size_t)PP*256*BB*NN];    // (p,m,b,n)
__device__ float g_attn[(size_t)BB*PP*NN*NN];   // (b,p,i,j)
__device__ float g_y[(size_t)PP*CC*BB*NN];      // (p,c,b,i)  y = xd @ attn^T
__device__ float g_ao[(size_t)PP*CC*BB*NN];     // (p,c,b,i)
__device__ float g_gap[(size_t)PP*CC*BB];       // (p,c,b)
__device__ float g_h1[(size_t)PP*C4*BB];        // (p,d,b)
__device__ float g_cw[(size_t)PP*CC*BB];        // (p,c,b)
__device__ float g_wgt[BB*PP];

// ---------------- K0: fold depthwise into QK weights + bias ----------------
__global__ void prep_wqk_kernel(const float* __restrict__ qw, const float* __restrict__ dwqw,
                                const float* __restrict__ dwqb, const float* __restrict__ qb,
                                const float* __restrict__ kw, const float* __restrict__ dwkw,
                                const float* __restrict__ dwkb, const float* __restrict__ kb)
{
    int bid = blockIdx.x;           // 0..767
    int p = bid / 256, m = bid % 256;
    const float *wsrc, *dww, *dwb; float bias0;
    if (m < 128) { wsrc = qw + ((size_t)p*128 + m)*CC; dww = dwqw + (size_t)p*CC; dwb = dwqb + (size_t)p*CC; bias0 = qb[p*128+m]; }
    else         { wsrc = kw + ((size_t)p*128 + (m-128))*CC; dww = dwkw + (size_t)p*CC; dwb = dwkb + (size_t)p*CC; bias0 = kb[p*128+(m-128)]; }
    float* wdst = g_wqk + ((size_t)p*256 + m)*CC;
    float acc = 0.f;
    for (int c = threadIdx.x; c < CC; c += 256) {
        float w = wsrc[c];
        wdst[c] = w * dww[c];
        acc += w * dwb[c];
    }
    __shared__ float red[256];
    red[threadIdx.x] = acc; __syncthreads();
    for (int s = 128; s > 0; s >>= 1) { if (threadIdx.x < s) red[threadIdx.x] += red[threadIdx.x+s]; __syncthreads(); }
    if (threadIdx.x == 0) g_bqk[p*256 + m] = bias0 + red[0];
}

// ---------------- K1: 2x2 average pool + per-row mean ----------------
__global__ __launch_bounds__(256) void downsample_kernel(const float* __restrict__ x)
{
    int gw = blockIdx.x * 8 + (threadIdx.x >> 5);
    int lane = threadIdx.x & 31;
    int wl = threadIdx.x >> 5;
    int b = gw / (PP*CC);
    int rem = gw % (PP*CC);
    int p = rem / CC;
    int c = rem % CC;
    const float* src = x + ((((size_t)b*CC + c)*HH) + (size_t)p*PHH) * WW;   // 384 contiguous floats
    __shared__ float s[8][384];
    float* sw = s[wl];
    float sum = 0.f;
#pragma unroll
    for (int t = 0; t < 12; t++) { float v = src[lane + t*32]; sw[lane + t*32] = v; sum += v; }
#pragma unroll
    for (int o = 16; o > 0; o >>= 1) sum += __shfl_xor_sync(0xffffffffu, sum, o);
    __syncwarp();
    float* dst = g_xd + (((size_t)p*CC + c)*BB + b)*NN;
#pragma unroll
    for (int t = 0; t < 3; t++) {
        int n = lane + t*32;
        int hd = n / WD, wd = n % WD;
        int base = (hd*2)*WW + wd*2;
        dst[n] = 0.25f * (sw[base] + sw[base+1] + sw[base+WW] + sw[base+WW+1]);
    }
    if (lane == 0) g_xmean[((size_t)p*CC + c)*BB + b] = sum * (1.0f/384.0f);
}

// ---------------- SGEMM: C[p] = A[p](MxK) @ B[p](KxN) + bias[p], 128x128x8 double-buffered ----------------
__global__ __launch_bounds__(256, 2) void sgemm_bias_kernel(
    const float* __restrict__ Ag, const float* __restrict__ Bg,
    const float* __restrict__ biasg, float* __restrict__ Cg,
    int M, int N, int K)
{
    int p = blockIdx.z;
    const float* A = Ag + (size_t)p*M*K;
    const float* Bp = Bg + (size_t)p*K*N;
    const float* bias = biasg + (size_t)p*M;
    float* Cm = Cg + (size_t)p*M*N;

    int bm = blockIdx.y * 128;
    int bnn = blockIdx.x * 128;
    int tid = threadIdx.x;

    __shared__ float As[2][8][128];
    __shared__ float Bs[2][8][128];

    int a_m = tid >> 1;             // 0..127
    int a_k = (tid & 1) * 4;        // 0 or 4
    int b_k = tid >> 5;             // 0..7
    int b_n = (tid & 31) * 4;

    int cm = (tid >> 4) * 8;
    int cn = (tid & 15) * 8;

    const float* Aptr = A + (size_t)(bm + a_m)*K + a_k;
    const float* Bptr = Bp + (size_t)b_k*N + bnn + b_n;

    float acc[8][8];
#pragma unroll
    for (int i = 0; i < 8; i++)
#pragma unroll
        for (int j = 0; j < 8; j++) acc[i][j] = 0.f;

    float4 av = *(const float4*)(Aptr);
    float4 bv = *(const float4*)(Bptr);
    As[0][a_k+0][a_m] = av.x; As[0][a_k+1][a_m] = av.y; As[0][a_k+2][a_m] = av.z; As[0][a_k+3][a_m] = av.w;
    *(float4*)&Bs[0][b_k][b_n] = bv;
    __syncthreads();

    int buf = 0;
    for (int k0 = 0; k0 < K; k0 += 8) {
        bool nxt = (k0 + 8) < K;
        float4 an, bn4;
        if (nxt) {
            an  = *(const float4*)(Aptr + k0 + 8);
            bn4 = *(const float4*)(Bptr + (size_t)(k0 + 8)*N);
        }
#pragma unroll
        for (int kk = 0; kk < 8; kk++) {
            float ar[8], br[8];
            *(float4*)(ar)   = *(const float4*)&As[buf][kk][cm];
            *(float4*)(ar+4) = *(const float4*)&As[buf][kk][cm+4];
            *(float4*)(br)   = *(const float4*)&Bs[buf][kk][cn];
            *(float4*)(br+4) = *(const float4*)&Bs[buf][kk][cn+4];
#pragma unroll
            for (int i = 0; i < 8; i++)
#pragma unroll
                for (int j = 0; j < 8; j++)
                    acc[i][j] = fmaf(ar[i], br[j], acc[i][j]);
        }
        if (nxt) {
            int nb = buf ^ 1;
            As[nb][a_k+0][a_m] = an.x; As[nb][a_k+1][a_m] = an.y; As[nb][a_k+2][a_m] = an.z; As[nb][a_k+3][a_m] = an.w;
            *(float4*)&Bs[nb][b_k][b_n] = bn4;
            __syncthreads();
            buf = nb;
        }
    }

#pragma unroll
    for (int i = 0; i < 8; i++) {
        int m = bm + cm + i;
        float bvv = bias[m];
        float* cp = Cm + (size_t)m*N + bnn + cn;
        float4 o0 = { acc[i][0]+bvv, acc[i][1]+bvv, acc[i][2]+bvv, acc[i][3]+bvv };
        float4 o1 = { acc[i][4]+bvv, acc[i][5]+bvv, acc[i][6]+bvv, acc[i][7]+bvv };
        *(float4*)cp = o0;
        *(float4*)(cp+4) = o1;
    }
}

// ---------------- K3a: energy + softmax (one block per (b,p)) ----------------
__global__ __launch_bounds__(256) void attn_kernel()
{
    int b = blockIdx.x / PP, p = blockIdx.x % PP;
    __shared__ float qs[8][96], ks[8][96];
    __shared__ float es[96][97];
    __shared__ float rinv[96];
    int tid = threadIdx.x;
    int tx = tid & 15, ty = tid >> 4;
    int n0 = tx*6, m0 = ty*6;
    float acc[6][6];
#pragma unroll
    for (int u = 0; u < 6; u++)
#pragma unroll
        for (int v = 0; v < 6; v++) acc[u][v] = 0.f;

    const float* qbase = g_qk + (size_t)p*256*BN + (size_t)b*NN;

    for (int i0 = 0; i0 < ICC; i0 += 8) {
        for (int t = tid; t < 8*96; t += 256) {
            int r = t / 96, col = t % 96;
            qs[r][col] = qbase[(size_t)(i0 + r)*BN + col];
            ks[r][col] = qbase[(size_t)(128 + i0 + r)*BN + col];
        }
        __syncthreads();
#pragma unroll
        for (int ii = 0; ii < 8; ii++) {
            float a[6], bb[6];
#pragma unroll
            for (int u = 0; u < 6; u++) a[u] = qs[ii][n0+u];
#pragma unroll
            for (int v = 0; v < 6; v++) bb[v] = ks[ii][m0+v];
#pragma unroll
            for (int u = 0; u < 6; u++)
#pragma unroll
                for (int v = 0; v < 6; v++) acc[u][v] = fmaf(a[u], bb[v], acc[u][v]);
        }
        __syncthreads();
    }
#pragma unroll
    for (int u = 0; u < 6; u++)
#pragma unroll
        for (int v = 0; v < 6; v++) es[n0+u][m0+v] = acc[u][v];
    __syncthreads();

    if (tid < 96) {
        float mx = -1e30f;
        for (int m = 0; m < 96; m++) mx = fmaxf(mx, es[tid][m]);
        float s = 0.f;
        for (int m = 0; m < 96; m++) { float e = expf(es[tid][m] - mx); es[tid][m] = e; s += e; }
        rinv[tid] = 1.0f / s;
    }
    __syncthreads();
    float* adst = g_attn + (size_t)(b*PP + p)*NN*NN;
    for (int t = tid; t < 96*96; t += 256) {
        int r = t / 96, m = t % 96;
        adst[t] = es[r][m] * rinv[r];
    }
}

// ---------------- K3b: y[c,i] = sum_j xd[c,j] * attn[i,j] ----------------
__global__ __launch_bounds__(256) void y_kernel()
{
    int bp = blockIdx.x;
    int b = bp / PP, p = bp % PP;
    int cb = blockIdx.y * 128;
    __shared__ float att[96][17];
    __shared__ float xs[128][17];
    int tid = threadIdx.x;
    int tx = tid & 15, ty = tid >> 4;
    int i0 = tx*6, c0 = ty*8;
    float acc[8][6];
#pragma unroll
    for (int u = 0; u < 8; u++)
#pragma unroll
        for (int v = 0; v < 6; v++) acc[u][v] = 0.f;

    const float* asrc = g_attn + (size_t)(b*PP + p)*NN*NN;
    const float* xsrc = g_xd + (((size_t)p*CC + cb)*BB + b)*NN;

    for (int j0 = 0; j0 < 96; j0 += 16) {
        for (int t = tid; t < 96*16; t += 256) {
            int r = t >> 4, jc = t & 15;
            att[r][jc] = asrc[r*96 + j0 + jc];
        }
        for (int t = tid; t < 128*16; t += 256) {
            int r = t >> 4, jc = t & 15;
            xs[r][jc] = xsrc[(size_t)r*BN + j0 + jc];
        }
        __syncthreads();
#pragma unroll
        for (int jj = 0; jj < 16; jj++) {
            float ar[8], br[6];
#pragma unroll
            for (int u = 0; u < 8; u++) ar[u] = xs[c0+u][jj];
#pragma unroll
            for (int v = 0; v < 6; v++) br[v] = att[i0+v][jj];
#pragma unroll
            for (int u = 0; u < 8; u++)
#pragma unroll
                for (int v = 0; v < 6; v++) acc[u][v] = fmaf(ar[u], br[v], acc[u][v]);
        }
        __syncthreads();
    }
    float* ydst = g_y + (((size_t)p*CC + cb)*BB + b)*NN;
#pragma unroll
    for (int u = 0; u < 8; u++)
#pragma unroll
        for (int v = 0; v < 6; v++)
            ydst[(size_t)(c0+u)*BN + i0 + v] = acc[u][v];
}

// ---------------- K4: gap = pa_gamma * mean_n(ao) + xmean ----------------
__global__ __launch_bounds__(256) void gap_kernel(const float* __restrict__ pa_gamma)
{
    int idx = blockIdx.x * 8 + (threadIdx.x >> 5);   // (p*C+c)*B + b
    int lane = threadIdx.x & 31;
    int pc = idx / BB;
    int p = pc / CC;
    const float* src = g_ao + (size_t)idx*NN;
    float s = 0.f;
#pragma unroll
    for (int t = 0; t < 3; t++) s += src[lane + t*32];
#pragma unroll
    for (int o = 16; o > 0; o >>= 1) s += __shfl_xor_sync(0xffffffffu, s, o);
    if (lane == 0) g_gap[idx] = pa_gamma[p] * (s * (1.0f/96.0f)) + g_xmean[idx];
}

// ---------------- K5: small batched GEMV (N = B = 32) with activation ----------------
__global__ __launch_bounds__(256) void mlp_kernel(const float* __restrict__ Ag, const float* __restrict__ Xg,
                                                  const float* __restrict__ biasg, float* __restrict__ outg,
                                                  int M, int K, int act)
{
    int p = blockIdx.y;
    const float* A = Ag + (size_t)p*M*K;
    const float* X = Xg + (size_t)p*K*BB;
    const float* bias = biasg + (size_t)p*M;
    float* out = outg + (size_t)p*M*BB;
    int m0 = blockIdx.x * 128;
    int tid = threadIdx.x;
    int bb = tid & 31, g = tid >> 5;
    __shared__ float xsm[32][33];
    __shared__ float wsm[128][33];
    float acc[16];
#pragma unroll
    for (int r = 0; r < 16; r++) acc[r] = 0.f;

    for (int k0 = 0; k0 < K; k0 += 32) {
        for (int t = tid; t < 32*32; t += 256) { int kk = t >> 5, b2 = t & 31; xsm[kk][b2] = X[(size_t)(k0+kk)*BB + b2]; }
        for (int t = tid; t < 128*32; t += 256) { int r = t >> 5, kk = t & 31; wsm[r][kk] = A[(size_t)(m0+r)*K + k0 + kk]; }
        __syncthreads();
#pragma unroll
        for (int kk = 0; kk < 32; kk++) {
            float xv = xsm[kk][bb];
#pragma unroll
            for (int r = 0; r < 16; r++) acc[r] = fmaf(wsm[g*16+r][kk], xv, acc[r]);
        }
        __syncthreads();
    }
#pragma unroll
    for (int r = 0; r < 16; r++) {
        int m = m0 + g*16 + r;
        float v = acc[r] + bias[m];
        v = (act == 0) ? fmaxf(v, 0.f) : 1.f/(1.f + expf(-v));
        out[(size_t)m*BB + bb] = v;
    }
}

// ---------------- K6: modality gate ----------------
__global__ void gate_kernel(const float* __restrict__ w1, const float* __restrict__ b1,
                            const float* __restrict__ w2, const float* __restrict__ b2,
                            const int* __restrict__ modality)
{
    int t = threadIdx.x;
    if (t >= BB*PP) return;
    int b = t / PP, p = t % PP;
    float mf = (float)modality[b];
    float s = b2[p];
#pragma unroll
    for (int j = 0; j < 12; j++) {
        float g1 = fmaxf(mf * w1[j] + b1[j], 0.f);
        s += g1 * w2[p*12 + j];
    }
    g_wgt[t] = 1.f/(1.f + expf(-s));
}

// ---------------- K7: fused bilinear upsample + residual + channel att + modality gate ----------------
__global__ __launch_bounds__(256) void final_kernel(const float* __restrict__ x,
                                                    const float* __restrict__ pa_gamma,
                                                    const float* __restrict__ ca_gamma,
                                                    float* __restrict__ out)
{
    int gw = blockIdx.x * 8 + (threadIdx.x >> 5);
    int lane = threadIdx.x & 31;
    int wl = threadIdx.x >> 5;
    int b = gw / (PP*CC);
    int rem = gw % (PP*CC);
    int p = rem / CC;
    int c = rem % CC;
    __shared__ float aos[8][96];
    const float* asrc = g_ao + (((size_t)p*CC + c)*BB + b)*NN;
#pragma unroll
    for (int t = 0; t < 3; t++) aos[wl][lane + t*32] = asrc[lane + t*32];
    __syncwarp();

    float wgt = g_wgt[b*PP + p];
    float cwv = g_cw[((size_t)p*CC + c)*BB + b];
    float fac = (1.f + ca_gamma[p]*cwv) * wgt;
    float gamma = pa_gamma[p];
    size_t base = (((size_t)b*CC + c)*HH + (size_t)p*PHH) * WW;

#pragma unroll
    for (int t = 0; t < 12; t++) {
        int idx = lane + t*32;
        int ph = idx / WW, w = idx % WW;
        int ih = (ph - 1) >> 1;
        float th = (ph & 1) ? 0.25f : 0.75f;
        int r0 = ih < 0 ? 0 : ih;
        int r1 = (ih + 1 > HD-1) ? (HD-1) : (ih + 1);
        int iw = (w - 1) >> 1;
        float tw = (w & 1) ? 0.25f : 0.75f;
        int q0 = iw < 0 ? 0 : iw;
        int q1 = (iw + 1 > WD-1) ? (WD-1) : (iw + 1);
        float up = (1.f - th)*((1.f - tw)*aos[wl][r0*WD+q0] + tw*aos[wl][r0*WD+q1])
                 +        th *((1.f - tw)*aos[wl][r1*WD+q0] + tw*aos[wl][r1*WD+q1]);
        float xv = x[base + idx];
        float pa = gamma*up + xv;
        out[base + idx] = xv*(1.f - wgt) + pa*fac;
    }
}

// ---------------- host orchestration ----------------
extern "C" void kernel_launch(void* const* d_in, const int* in_sizes, int n_in,
                              void* d_out, int out_size)
{
    const float* x        = (const float*)d_in[0];
    const float* dwq_w    = (const float*)d_in[1];
    const float* dwq_b    = (const float*)d_in[2];
    const float* q_w      = (const float*)d_in[3];
    const float* q_b      = (const float*)d_in[4];
    const float* dwk_w    = (const float*)d_in[5];
    const float* dwk_b    = (const float*)d_in[6];
    const float* k_w      = (const float*)d_in[7];
    const float* k_b      = (const float*)d_in[8];
    const float* v_w      = (const float*)d_in[9];
    const float* v_b      = (const float*)d_in[10];
    const float* pa_gamma = (const float*)d_in[11];
    const float* fc1_w    = (const float*)d_in[12];
    const float* fc1_b    = (const float*)d_in[13];
    const float* fc2_w    = (const float*)d_in[14];
    const float* fc2_b    = (const float*)d_in[15];
    const float* ca_gamma = (const float*)d_in[16];
    const float* gate_w1  = (const float*)d_in[17];
    const float* gate_b1  = (const float*)d_in[18];
    const float* gate_w2  = (const float*)d_in[19];
    const float* gate_b2  = (const float*)d_in[20];
    const int*   modality = (const int*)d_in[21];
    float* out = (float*)d_out;

    float *p_wqk, *p_bqk, *p_xd, *p_qk, *p_y, *p_ao, *p_gap, *p_h1, *p_cw;
    cudaGetSymbolAddress((void**)&p_wqk, g_wqk);
    cudaGetSymbolAddress((void**)&p_bqk, g_bqk);
    cudaGetSymbolAddress((void**)&p_xd,  g_xd);
    cudaGetSymbolAddress((void**)&p_qk,  g_qk);
    cudaGetSymbolAddress((void**)&p_y,   g_y);
    cudaGetSymbolAddress((void**)&p_ao,  g_ao);
    cudaGetSymbolAddress((void**)&p_gap, g_gap);
    cudaGetSymbolAddress((void**)&p_h1,  g_h1);
    cudaGetSymbolAddress((void**)&p_cw,  g_cw);

    // K0: effective QK weights/bias
    prep_wqk_kernel<<<PP*256, 256>>>(q_w, dwq_w, dwq_b, q_b, k_w, dwk_w, dwk_b, k_b);

    // K1: downsample + xmean
    downsample_kernel<<<(BB*PP*CC)/8, 256>>>(x);

    // K2a: QK GEMM  (M=256, N=3072, K=2048) per p
    sgemm_bias_kernel<<<dim3(BN/128, 256/128, PP), 256>>>(p_wqk, p_xd, p_bqk, p_qk, 256, BN, CC);

    // K3a: energy + softmax
    attn_kernel<<<BB*PP, 256>>>();

    // K3b: y = xd @ attn^T
    y_kernel<<<dim3(BB*PP, CC/128), 256>>>();

    // K2b: AO GEMM  ao = Vw @ y + vb  (M=2048, N=3072, K=2048) per p  — dominant cost
    sgemm_bias_kernel<<<dim3(BN/128, CC/128, PP), 256>>>(v_w, p_y, v_b, p_ao, CC, BN, CC);

    // K4: gap
    gap_kernel<<<(PP*CC*BB)/8, 256>>>(pa_gamma);

    // K5: channel-attention MLP
    mlp_kernel<<<dim3(C4/128, PP), 256>>>(fc1_w, p_gap, fc1_b, p_h1, C4, CC, 0);
    mlp_kernel<<<dim3(CC/128, PP), 256>>>(fc2_w, p_h1, fc2_b, p_cw, CC, C4, 1);

    // K6: modality gate
    gate_kernel<<<1, 128>>>(gate_w1, gate_b1, gate_w2, gate_b2, modality);

    // K7: fused upsample + residuals + gating -> output
    final_kernel<<<(BB*PP*CC)/8, 256>>>(x, pa_gamma, ca_gamma, out);
}

// round 4
// speedup vs baseline: 2.0416x; 2.0416x over previous
#include <cuda_runtime.h>
#include <cuda_bf16.h>
#include <math.h>
#include <stdint.h>

#define BB 32
#define CC 2048
#define HH 48
#define WW 24
#define PP 3
#define PHH 16
#define HD 8
#define WD 12
#define NN 96
#define ICC 128
#define C4 512
#define BN (BB*NN)   // 3072

// ---------------- scratch ----------------
__device__ __nv_bfloat16 g_xd_h[(size_t)PP*CC*BN];
__device__ __nv_bfloat16 g_xd_l[(size_t)PP*CC*BN];
__device__ __nv_bfloat16 g_wqk_h[(size_t)PP*256*CC];
__device__ __nv_bfloat16 g_wqk_l[(size_t)PP*256*CC];
__device__ __nv_bfloat16 g_vw_h[(size_t)PP*CC*CC];
__device__ __nv_bfloat16 g_vw_l[(size_t)PP*CC*CC];
__device__ __nv_bfloat16 g_at_h[(size_t)BB*PP*NN*NN + 64];
__device__ __nv_bfloat16 g_at_l[(size_t)BB*PP*NN*NN + 64];
__device__ __nv_bfloat16 g_y_h[(size_t)PP*CC*BN];
__device__ __nv_bfloat16 g_y_l[(size_t)PP*CC*BN];
__device__ float g_xmean[(size_t)PP*CC*BB];
__device__ float g_bqk[PP*256];
__device__ float g_qk[(size_t)PP*256*BN];
__device__ float g_ao[(size_t)PP*CC*BN];
__device__ float g_gap[(size_t)PP*CC*BB];
__device__ float g_h1[(size_t)PP*C4*BB];
__device__ float g_cw[(size_t)PP*CC*BB];
__device__ float g_wgt[BB*PP];

// ---------------- PTX helpers ----------------
__device__ __forceinline__ uint32_t s2u(const void* p) {
    uint32_t a;
    asm("{ .reg .u64 t; cvta.to.shared.u64 t, %1; cvt.u32.u64 %0, t; }" : "=r"(a) : "l"(p));
    return a;
}
__device__ __forceinline__ void cpa16(uint32_t s, const void* g) {
    asm volatile("cp.async.ca.shared.global [%0], [%1], 16;" :: "r"(s), "l"(g));
}
__device__ __forceinline__ void cpa16z(uint32_t s, const void* g, int sz) {
    asm volatile("cp.async.ca.shared.global [%0], [%1], 16, %2;" :: "r"(s), "l"(g), "r"(sz));
}
#define CP_COMMIT() asm volatile("cp.async.commit_group;" ::: "memory")
#define CP_WAIT1()  asm volatile("cp.async.wait_group 1;" ::: "memory")

__device__ __forceinline__ void ldsm4(uint32_t* r, uint32_t a) {
    asm volatile("ldmatrix.sync.aligned.m8n8.x4.shared.b16 {%0,%1,%2,%3}, [%4];"
                 : "=r"(r[0]), "=r"(r[1]), "=r"(r[2]), "=r"(r[3]) : "r"(a));
}
__device__ __forceinline__ void ldsm4t(uint32_t* r, uint32_t a) {
    asm volatile("ldmatrix.sync.aligned.m8n8.x4.trans.shared.b16 {%0,%1,%2,%3}, [%4];"
                 : "=r"(r[0]), "=r"(r[1]), "=r"(r[2]), "=r"(r[3]) : "r"(a));
}
__device__ __forceinline__ void mma16816(float* c, const uint32_t* a, const uint32_t* b) {
    asm volatile("mma.sync.aligned.m16n8k16.row.col.f32.bf16.bf16.f32 "
                 "{%0,%1,%2,%3}, {%4,%5,%6,%7}, {%8,%9}, {%0,%1,%2,%3};"
                 : "+f"(c[0]), "+f"(c[1]), "+f"(c[2]), "+f"(c[3])
                 : "r"(a[0]), "r"(a[1]), "r"(a[2]), "r"(a[3]), "r"(b[0]), "r"(b[1]));
}

// SMEM geometry for the mma GEMMs
#define A_TB 10240           // 128 x 40 bf16
#define B_TB 8704            // 32 x 136 bf16
#define GBUF (2*A_TB + 2*B_TB)   // 37888
#define SMEM_G (2*GBUF)          // 75776

// shared tile compute: warp (m_off x 32) x (n_off x 64), one k32 chunk
__device__ __forceinline__ void tile_compute(uint32_t sbase, int lane, int m_off, int n_off,
                                             float acc[2][8][4]) {
#pragma unroll
    for (int kh = 0; kh < 2; kh++) {
        uint32_t a_h[2][4], a_l[2][4];
#pragma unroll
        for (int tm = 0; tm < 2; tm++) {
            uint32_t off = ((m_off + tm*16 + (lane & 15))*40 + kh*16 + (lane >> 4)*8)*2;
            ldsm4(a_h[tm], sbase + off);
            ldsm4(a_l[tm], sbase + A_TB + off);
        }
#pragma unroll
        for (int g = 0; g < 4; g++) {
            uint32_t bh4[4], bl4[4];
            uint32_t off = ((kh*16 + (lane & 15))*136 + n_off + g*16 + (lane >> 4)*8)*2;
            ldsm4t(bh4, sbase + 2*A_TB + off);
            ldsm4t(bl4, sbase + 2*A_TB + B_TB + off);
#pragma unroll
            for (int tm = 0; tm < 2; tm++) {
#pragma unroll
                for (int h2 = 0; h2 < 2; h2++) {
                    int j = g*2 + h2;
                    mma16816(acc[tm][j], a_h[tm], &bh4[h2*2]);
                    mma16816(acc[tm][j], a_h[tm], &bl4[h2*2]);
                    mma16816(acc[tm][j], a_l[tm], &bh4[h2*2]);
                }
            }
        }
    }
}

__device__ __forceinline__ void stage_load(uint32_t sbase,
    const __nv_bfloat16* Ah, const __nv_bfloat16* Al,
    const __nv_bfloat16* Bh, const __nv_bfloat16* Bl,
    int kt, int K, int N, int tid)
{
#pragma unroll
    for (int i = 0; i < 2; i++) {
        int ch = tid + i*256;
        int r = ch >> 2, c8 = ch & 3;
        size_t go = (size_t)r*K + kt*32 + c8*8;
        uint32_t sa = sbase + (r*40 + c8*8)*2;
        cpa16(sa, Ah + go);
        cpa16(sa + A_TB, Al + go);
    }
#pragma unroll
    for (int i = 0; i < 2; i++) {
        int ch = tid + i*256;
        int r = ch >> 4, c8 = ch & 15;
        size_t go = (size_t)(kt*32 + r)*N + c8*8;
        uint32_t sbB = sbase + 2*A_TB + (r*136 + c8*8)*2;
        cpa16(sbB, Bh + go);
        cpa16(sbB + B_TB, Bl + go);
    }
}

// ================= generic MMA GEMM: C = A(MxK) @ B(KxN) + bias =================
__global__ __launch_bounds__(256, 2) void gemm_mma_kernel(
    const __nv_bfloat16* __restrict__ Ah_, const __nv_bfloat16* __restrict__ Al_,
    const __nv_bfloat16* __restrict__ Bh_, const __nv_bfloat16* __restrict__ Bl_,
    const float* __restrict__ bias_, float* __restrict__ C_,
    int M, int N, int K, size_t az, size_t bz, size_t cz, int biasz)
{
    extern __shared__ char smem[];
    uint32_t sb = s2u(smem);
    int tid = threadIdx.x, lane = tid & 31, wid = tid >> 5;
    int p = blockIdx.z;
    int bm = blockIdx.y * 128, bn = blockIdx.x * 128;
    const __nv_bfloat16* Ah = Ah_ + (size_t)p*az + (size_t)bm*K;
    const __nv_bfloat16* Al = Al_ + (size_t)p*az + (size_t)bm*K;
    const __nv_bfloat16* Bh = Bh_ + (size_t)p*bz + bn;
    const __nv_bfloat16* Bl = Bl_ + (size_t)p*bz + bn;
    const float* bias = bias_ + (size_t)p*biasz + bm;
    float* C = C_ + (size_t)p*cz + (size_t)bm*N + bn;
    int m_off = (wid & 3)*32, n_off = (wid >> 2)*64;

    float acc[2][8][4];
#pragma unroll
    for (int a = 0; a < 2; a++)
#pragma unroll
        for (int b = 0; b < 8; b++)
#pragma unroll
            for (int c = 0; c < 4; c++) acc[a][b][c] = 0.f;

    int NK = K / 32;
    stage_load(sb, Ah, Al, Bh, Bl, 0, K, N, tid);
    CP_COMMIT();
    if (NK > 1) stage_load(sb + GBUF, Ah, Al, Bh, Bl, 1, K, N, tid);
    CP_COMMIT();

    for (int kt = 0; kt < NK; kt++) {
        CP_WAIT1();
        __syncthreads();
        uint32_t buf = sb + (kt & 1)*GBUF;
        tile_compute(buf, lane, m_off, n_off, acc);
        __syncthreads();
        if (kt + 2 < NK) stage_load(buf, Ah, Al, Bh, Bl, kt + 2, K, N, tid);
        CP_COMMIT();
    }

    int ri = lane >> 2, ci = (lane & 3)*2;
#pragma unroll
    for (int tm = 0; tm < 2; tm++) {
#pragma unroll
        for (int h = 0; h < 2; h++) {
            int row = m_off + tm*16 + ri + h*8;
            float bv = bias[row];
            float* crow = C + (size_t)row*N;
#pragma unroll
            for (int j = 0; j < 8; j++) {
                float2 o;
                o.x = acc[tm][j][h*2]   + bv;
                o.y = acc[tm][j][h*2+1] + bv;
                *(float2*)(crow + n_off + j*8 + ci) = o;
            }
        }
    }
}

// ================= y GEMM (per b,p): y[c,i] = sum_j xd[c,j] * aT[j,i]; bf16 hi/lo out =================
__global__ __launch_bounds__(256, 2) void y_mma_kernel()
{
    extern __shared__ char smem[];
    uint32_t sb = s2u(smem);
    int tid = threadIdx.x, lane = tid & 31, wid = tid >> 5;
    int bm = blockIdx.x * 128;
    int b = blockIdx.y, p = blockIdx.z;
    const __nv_bfloat16* Ah = g_xd_h + (size_t)p*CC*BN + (size_t)bm*BN + b*NN;
    const __nv_bfloat16* Al = g_xd_l + (size_t)p*CC*BN + (size_t)bm*BN + b*NN;
    const __nv_bfloat16* Bh = g_at_h + (size_t)(b*PP + p)*NN*NN;
    const __nv_bfloat16* Bl = g_at_l + (size_t)(b*PP + p)*NN*NN;
    int m_off = (wid & 3)*32, n_off = (wid >> 2)*64;

    float acc[2][8][4];
#pragma unroll
    for (int a = 0; a < 2; a++)
#pragma unroll
        for (int b2 = 0; b2 < 8; b2++)
#pragma unroll
            for (int c = 0; c < 4; c++) acc[a][b2][c] = 0.f;

    const int NK = 3;   // K = 96
#pragma unroll
    for (int pre = 0; pre < 2; pre++) {
        uint32_t sbase = sb + pre*GBUF;
#pragma unroll
        for (int i = 0; i < 2; i++) {
            int ch = tid + i*256;
            int r = ch >> 2, c8 = ch & 3;
            size_t go = (size_t)r*BN + pre*32 + c8*8;
            uint32_t sa = sbase + (r*40 + c8*8)*2;
            cpa16(sa, Ah + go);
            cpa16(sa + A_TB, Al + go);
        }
#pragma unroll
        for (int i = 0; i < 2; i++) {
            int ch = tid + i*256;
            int r = ch >> 4, c8 = ch & 15;
            int sz = (c8 < 12) ? 16 : 0;
            size_t go = (size_t)(pre*32 + r)*NN + ((c8 < 12) ? c8*8 : 0);
            uint32_t sbB = sbase + 2*A_TB + (r*136 + c8*8)*2;
            cpa16z(sbB, Bh + go, sz);
            cpa16z(sbB + B_TB, Bl + go, sz);
        }
        CP_COMMIT();
    }
    for (int kt = 0; kt < NK; kt++) {
        CP_WAIT1();
        __syncthreads();
        uint32_t buf = sb + (kt & 1)*GBUF;
        tile_compute(buf, lane, m_off, n_off, acc);
        __syncthreads();
        if (kt + 2 < NK) {
            int ks = kt + 2;
#pragma unroll
            for (int i = 0; i < 2; i++) {
                int ch = tid + i*256;
                int r = ch >> 2, c8 = ch & 3;
                size_t go = (size_t)r*BN + ks*32 + c8*8;
                uint32_t sa = buf + (r*40 + c8*8)*2;
                cpa16(sa, Ah + go);
                cpa16(sa + A_TB, Al + go);
            }
#pragma unroll
            for (int i = 0; i < 2; i++) {
                int ch = tid + i*256;
                int r = ch >> 4, c8 = ch & 15;
                int sz = (c8 < 12) ? 16 : 0;
                size_t go = (size_t)(ks*32 + r)*NN + ((c8 < 12) ? c8*8 : 0);
                uint32_t sbB = buf + 2*A_TB + (r*136 + c8*8)*2;
                cpa16z(sbB, Bh + go, sz);
                cpa16z(sbB + B_TB, Bl + go, sz);
            }
        }
        CP_COMMIT();
    }

    int ri = lane >> 2, ci = (lane & 3)*2;
    __nv_bfloat16* yh = g_y_h + (size_t)p*CC*BN + b*NN;
    __nv_bfloat16* yl = g_y_l + (size_t)p*CC*BN + b*NN;
#pragma unroll
    for (int tm = 0; tm < 2; tm++) {
#pragma unroll
        for (int h = 0; h < 2; h++) {
            int row = bm + m_off + tm*16 + ri + h*8;
#pragma unroll
            for (int j = 0; j < 8; j++) {
                int col = n_off + j*8 + ci;
                if (col < NN) {
                    float v0 = acc[tm][j][h*2], v1 = acc[tm][j][h*2+1];
                    __nv_bfloat16 h0 = __float2bfloat16(v0);
                    __nv_bfloat16 h1 = __float2bfloat16(v1);
                    __nv_bfloat16 l0 = __float2bfloat16(v0 - __bfloat162float(h0));
                    __nv_bfloat16 l1 = __float2bfloat16(v1 - __bfloat162float(h1));
                    __nv_bfloat162 ph; ph.x = h0; ph.y = h1;
                    __nv_bfloat162 pl; pl.x = l0; pl.y = l1;
                    *(uint32_t*)(yh + (size_t)row*BN + col) = *(uint32_t*)&ph;
                    *(uint32_t*)(yl + (size_t)row*BN + col) = *(uint32_t*)&pl;
                }
            }
        }
    }
}

// ================= K0: fold depthwise into QK weights/bias (bf16 hi/lo out) =================
__global__ void prep_wqk_kernel(const float* __restrict__ qw, const float* __restrict__ dwqw,
                                const float* __restrict__ dwqb, const float* __restrict__ qb,
                                const float* __restrict__ kw, const float* __restrict__ dwkw,
                                const float* __restrict__ dwkb, const float* __restrict__ kb)
{
    int bid = blockIdx.x;
    int p = bid / 256, m = bid % 256;
    const float *wsrc, *dww, *dwb; float bias0;
    if (m < 128) { wsrc = qw + ((size_t)p*128 + m)*CC; dww = dwqw + (size_t)p*CC; dwb = dwqb + (size_t)p*CC; bias0 = qb[p*128+m]; }
    else         { wsrc = kw + ((size_t)p*128 + (m-128))*CC; dww = dwkw + (size_t)p*CC; dwb = dwkb + (size_t)p*CC; bias0 = kb[p*128+(m-128)]; }
    __nv_bfloat16* wh = g_wqk_h + ((size_t)p*256 + m)*CC;
    __nv_bfloat16* wl = g_wqk_l + ((size_t)p*256 + m)*CC;
    float acc = 0.f;
    for (int c = threadIdx.x; c < CC; c += 256) {
        float w = wsrc[c];
        float v = w * dww[c];
        __nv_bfloat16 h = __float2bfloat16(v);
        wh[c] = h;
        wl[c] = __float2bfloat16(v - __bfloat162float(h));
        acc += w * dwb[c];
    }
    __shared__ float red[256];
    red[threadIdx.x] = acc; __syncthreads();
    for (int s = 128; s > 0; s >>= 1) { if (threadIdx.x < s) red[threadIdx.x] += red[threadIdx.x+s]; __syncthreads(); }
    if (threadIdx.x == 0) g_bqk[p*256 + m] = bias0 + red[0];
}

// ================= K1: downsample + mean (bf16 hi/lo out) =================
__global__ __launch_bounds__(256) void downsample_kernel(const float* __restrict__ x)
{
    int gw = blockIdx.x * 8 + (threadIdx.x >> 5);
    int lane = threadIdx.x & 31;
    int wl = threadIdx.x >> 5;
    int b = gw / (PP*CC);
    int rem = gw % (PP*CC);
    int p = rem / CC;
    int c = rem % CC;
    const float* src = x + ((((size_t)b*CC + c)*HH) + (size_t)p*PHH) * WW;
    __shared__ float s[8][384];
    float* sw = s[wl];
    float sum = 0.f;
#pragma unroll
    for (int t = 0; t < 12; t++) { float v = src[lane + t*32]; sw[lane + t*32] = v; sum += v; }
#pragma unroll
    for (int o = 16; o > 0; o >>= 1) sum += __shfl_xor_sync(0xffffffffu, sum, o);
    __syncwarp();
    size_t dbase = ((size_t)p*CC + c)*BN + b*NN;
#pragma unroll
    for (int t = 0; t < 3; t++) {
        int n = lane + t*32;
        int hd = n / WD, wd = n % WD;
        int base = (hd*2)*WW + wd*2;
        float v = 0.25f * (sw[base] + sw[base+1] + sw[base+WW] + sw[base+WW+1]);
        __nv_bfloat16 h = __float2bfloat16(v);
        g_xd_h[dbase + n] = h;
        g_xd_l[dbase + n] = __float2bfloat16(v - __bfloat162float(h));
    }
    if (lane == 0) g_xmean[((size_t)p*CC + c)*BB + b] = sum * (1.0f/384.0f);
}

// ================= conv vw fp32 -> bf16 hi/lo =================
__global__ __launch_bounds__(256) void conv_vw_kernel(const float* __restrict__ vw)
{
    size_t i = ((size_t)blockIdx.x*256 + threadIdx.x)*4;
    float4 v = *(const float4*)(vw + i);
    __nv_bfloat16 h0 = __float2bfloat16(v.x), h1 = __float2bfloat16(v.y);
    __nv_bfloat16 h2 = __float2bfloat16(v.z), h3 = __float2bfloat16(v.w);
    __nv_bfloat162 a; a.x = h0; a.y = h1;
    __nv_bfloat162 b; b.x = h2; b.y = h3;
    uint2 hh = { *(uint32_t*)&a, *(uint32_t*)&b };
    __nv_bfloat162 c; c.x = __float2bfloat16(v.x - __bfloat162float(h0)); c.y = __float2bfloat16(v.y - __bfloat162float(h1));
    __nv_bfloat162 d; d.x = __float2bfloat16(v.z - __bfloat162float(h2)); d.y = __float2bfloat16(v.w - __bfloat162float(h3));
    uint2 ll = { *(uint32_t*)&c, *(uint32_t*)&d };
    *(uint2*)(g_vw_h + i) = hh;
    *(uint2*)(g_vw_l + i) = ll;
}

// ================= K3a: energy + softmax; write transposed attn as bf16 hi/lo =================
__global__ __launch_bounds__(256) void attn_kernel()
{
    int b = blockIdx.x / PP, p = blockIdx.x % PP;
    __shared__ float qs[8][96], ks[8][96];
    __shared__ float es[96][97];
    __shared__ float rinv[96];
    int tid = threadIdx.x;
    int tx = tid & 15, ty = tid >> 4;
    int n0 = tx*6, m0 = ty*6;
    float acc[6][6];
#pragma unroll
    for (int u = 0; u < 6; u++)
#pragma unroll
        for (int v = 0; v < 6; v++) acc[u][v] = 0.f;

    const float* qbase = g_qk + (size_t)p*256*BN + (size_t)b*NN;

    for (int i0 = 0; i0 < ICC; i0 += 8) {
        for (int t = tid; t < 8*96; t += 256) {
            int r = t / 96, col = t % 96;
            qs[r][col] = qbase[(size_t)(i0 + r)*BN + col];
            ks[r][col] = qbase[(size_t)(128 + i0 + r)*BN + col];
        }
        __syncthreads();
#pragma unroll
        for (int ii = 0; ii < 8; ii++) {
            float a[6], bb[6];
#pragma unroll
            for (int u = 0; u < 6; u++) a[u] = qs[ii][n0+u];
#pragma unroll
            for (int v = 0; v < 6; v++) bb[v] = ks[ii][m0+v];
#pragma unroll
            for (int u = 0; u < 6; u++)
#pragma unroll
                for (int v = 0; v < 6; v++) acc[u][v] = fmaf(a[u], bb[v], acc[u][v]);
        }
        __syncthreads();
    }
#pragma unroll
    for (int u = 0; u < 6; u++)
#pragma unroll
        for (int v = 0; v < 6; v++) es[n0+u][m0+v] = acc[u][v];
    __syncthreads();

    if (tid < 96) {
        float mx = -1e30f;
        for (int m = 0; m < 96; m++) mx = fmaxf(mx, es[tid][m]);
        float s = 0.f;
        for (int m = 0; m < 96; m++) { float e = expf(es[tid][m] - mx); es[tid][m] = e; s += e; }
        rinv[tid] = 1.0f / s;
    }
    __syncthreads();
    __nv_bfloat16* th = g_at_h + (size_t)(b*PP + p)*NN*NN;
    __nv_bfloat16* tl = g_at_l + (size_t)(b*PP + p)*NN*NN;
    for (int t = tid; t < 96*96; t += 256) {
        int i = t / 96, j = t % 96;
        float v = es[i][j] * rinv[i];
        __nv_bfloat16 h = __float2bfloat16(v);
        th[j*96 + i] = h;
        tl[j*96 + i] = __float2bfloat16(v - __bfloat162float(h));
    }
}

// ================= K4: gap =================
__global__ __launch_bounds__(256) void gap_kernel(const float* __restrict__ pa_gamma)
{
    int idx = blockIdx.x * 8 + (threadIdx.x >> 5);
    int lane = threadIdx.x & 31;
    int pc = idx / BB;
    int p = pc / CC;
    const float* src = g_ao + (size_t)idx*NN;
    float s = 0.f;
#pragma unroll
    for (int t = 0; t < 3; t++) s += src[lane + t*32];
#pragma unroll
    for (int o = 16; o > 0; o >>= 1) s += __shfl_xor_sync(0xffffffffu, s, o);
    if (lane == 0) g_gap[idx] = pa_gamma[p] * (s * (1.0f/96.0f)) + g_xmean[idx];
}

// ================= K5: batched MLP =================
__global__ __launch_bounds__(256) void mlp_kernel(const float* __restrict__ Ag, const float* __restrict__ Xg,
                                                  const float* __restrict__ biasg, float* __restrict__ outg,
                                                  int M, int K, int act)
{
    int p = blockIdx.y;
    const float* A = Ag + (size_t)p*M*K;
    const float* X = Xg + (size_t)p*K*BB;
    const float* bias = biasg + (size_t)p*M;
    float* out = outg + (size_t)p*M*BB;
    int m0 = blockIdx.x * 128;
    int tid = threadIdx.x;
    int bb = tid & 31, g = tid >> 5;
    __shared__ float xsm[32][33];
    __shared__ float wsm[128][33];
    float acc[16];
#pragma unroll
    for (int r = 0; r < 16; r++) acc[r] = 0.f;

    for (int k0 = 0; k0 < K; k0 += 32) {
        for (int t = tid; t < 32*32; t += 256) { int kk = t >> 5, b2 = t & 31; xsm[kk][b2] = X[(size_t)(k0+kk)*BB + b2]; }
        for (int t = tid; t < 128*32; t += 256) { int r = t >> 5, kk = t & 31; wsm[r][kk] = A[(size_t)(m0+r)*K + k0 + kk]; }
        __syncthreads();
#pragma unroll
        for (int kk = 0; kk < 32; kk++) {
            float xv = xsm[kk][bb];
#pragma unroll
            for (int r = 0; r < 16; r++) acc[r] = fmaf(wsm[g*16+r][kk], xv, acc[r]);
        }
        __syncthreads();
    }
#pragma unroll
    for (int r = 0; r < 16; r++) {
        int m = m0 + g*16 + r;
        float v = acc[r] + bias[m];
        v = (act == 0) ? fmaxf(v, 0.f) : 1.f/(1.f + expf(-v));
        out[(size_t)m*BB + bb] = v;
    }
}

// ================= K6: modality gate =================
__global__ void gate_kernel(const float* __restrict__ w1, const float* __restrict__ b1,
                            const float* __restrict__ w2, const float* __restrict__ b2,
                            const int* __restrict__ modality)
{
    int t = threadIdx.x;
    if (t >= BB*PP) return;
    int b = t / PP, p = t % PP;
    float mf = (float)modality[b];
    float s = b2[p];
#pragma unroll
    for (int j = 0; j < 12; j++) {
        float g1 = fmaxf(mf * w1[j] + b1[j], 0.f);
        s += g1 * w2[p*12 + j];
    }
    g_wgt[t] = 1.f/(1.f + expf(-s));
}

// ================= K7: fused upsample + residual + gates =================
__global__ __launch_bounds__(256) void final_kernel(const float* __restrict__ x,
                                                    const float* __restrict__ pa_gamma,
                                                    const float* __restrict__ ca_gamma,
                                                    float* __restrict__ out)
{
    int gw = blockIdx.x * 8 + (threadIdx.x >> 5);
    int lane = threadIdx.x & 31;
    int wl = threadIdx.x >> 5;
    int b = gw / (PP*CC);
    int rem = gw % (PP*CC);
    int p = rem / CC;
    int c = rem % CC;
    __shared__ float aos[8][96];
    const float* asrc = g_ao + (((size_t)p*CC + c)*BB + b)*NN;
#pragma unroll
    for (int t = 0; t < 3; t++) aos[wl][lane + t*32] = asrc[lane + t*32];
    __syncwarp();

    float wgt = g_wgt[b*PP + p];
    float cwv = g_cw[((size_t)p*CC + c)*BB + b];
    float fac = (1.f + ca_gamma[p]*cwv) * wgt;
    float gamma = pa_gamma[p];
    size_t base = (((size_t)b*CC + c)*HH + (size_t)p*PHH) * WW;

#pragma unroll
    for (int t = 0; t < 12; t++) {
        int idx = lane + t*32;
        int ph = idx / WW, w = idx % WW;
        int ih = (ph - 1) >> 1;
        float th = (ph & 1) ? 0.25f : 0.75f;
        int r0 = ih < 0 ? 0 : ih;
        int r1 = (ih + 1 > HD-1) ? (HD-1) : (ih + 1);
        int iw = (w - 1) >> 1;
        float tw = (w & 1) ? 0.25f : 0.75f;
        int q0 = iw < 0 ? 0 : iw;
        int q1 = (iw + 1 > WD-1) ? (WD-1) : (iw + 1);
        float up = (1.f - th)*((1.f - tw)*aos[wl][r0*WD+q0] + tw*aos[wl][r0*WD+q1])
                 +        th *((1.f - tw)*aos[wl][r1*WD+q0] + tw*aos[wl][r1*WD+q1]);
        float xv = x[base + idx];
        float pa = gamma*up + xv;
        out[base + idx] = xv*(1.f - wgt) + pa*fac;
    }
}

// ================= host =================
extern "C" void kernel_launch(void* const* d_in, const int* in_sizes, int n_in,
                              void* d_out, int out_size)
{
    const float* x        = (const float*)d_in[0];
    const float* dwq_w    = (const float*)d_in[1];
    const float* dwq_b    = (const float*)d_in[2];
    const float* q_w      = (const float*)d_in[3];
    const float* q_b      = (const float*)d_in[4];
    const float* dwk_w    = (const float*)d_in[5];
    const float* dwk_b    = (const float*)d_in[6];
    const float* k_w      = (const float*)d_in[7];
    const float* k_b      = (const float*)d_in[8];
    const float* v_w      = (const float*)d_in[9];
    const float* v_b      = (const float*)d_in[10];
    const float* pa_gamma = (const float*)d_in[11];
    const float* fc1_w    = (const float*)d_in[12];
    const float* fc1_b    = (const float*)d_in[13];
    const float* fc2_w    = (const float*)d_in[14];
    const float* fc2_b    = (const float*)d_in[15];
    const float* ca_gamma = (const float*)d_in[16];
    const float* gate_w1  = (const float*)d_in[17];
    const float* gate_b1  = (const float*)d_in[18];
    const float* gate_w2  = (const float*)d_in[19];
    const float* gate_b2  = (const float*)d_in[20];
    const int*   modality = (const int*)d_in[21];
    float* out = (float*)d_out;

    __nv_bfloat16 *p_wqk_h, *p_wqk_l, *p_xd_h, *p_xd_l, *p_vw_h, *p_vw_l, *p_y_h, *p_y_l;
    float *p_bqk, *p_qk, *p_ao, *p_gap, *p_h1, *p_cw;
    cudaGetSymbolAddress((void**)&p_wqk_h, g_wqk_h);
    cudaGetSymbolAddress((void**)&p_wqk_l, g_wqk_l);
    cudaGetSymbolAddress((void**)&p_xd_h,  g_xd_h);
    cudaGetSymbolAddress((void**)&p_xd_l,  g_xd_l);
    cudaGetSymbolAddress((void**)&p_vw_h,  g_vw_h);
    cudaGetSymbolAddress((void**)&p_vw_l,  g_vw_l);
    cudaGetSymbolAddress((void**)&p_y_h,   g_y_h);
    cudaGetSymbolAddress((void**)&p_y_l,   g_y_l);
    cudaGetSymbolAddress((void**)&p_bqk,   g_bqk);
    cudaGetSymbolAddress((void**)&p_qk,    g_qk);
    cudaGetSymbolAddress((void**)&p_ao,    g_ao);
    cudaGetSymbolAddress((void**)&p_gap,   g_gap);
    cudaGetSymbolAddress((void**)&p_h1,    g_h1);
    cudaGetSymbolAddress((void**)&p_cw,    g_cw);

    static bool attr_done = false;
    if (!attr_done) {
        cudaFuncSetAttribute(gemm_mma_kernel, cudaFuncAttributeMaxDynamicSharedMemorySize, SMEM_G);
        cudaFuncSetAttribute(y_mma_kernel,    cudaFuncAttributeMaxDynamicSharedMemorySize, SMEM_G);
        attr_done = true;
    }

    prep_wqk_kernel<<<PP*256, 256>>>(q_w, dwq_w, dwq_b, q_b, k_w, dwk_w, dwk_b, k_b);
    downsample_kernel<<<(BB*PP*CC)/8, 256>>>(x);
    conv_vw_kernel<<<(PP*CC*CC)/(256*4), 256>>>(v_w);

    // QK GEMM: qk[m, bn] = wqk[m,:] . xd[:, bn] + bqk   (M=256, N=3072, K=2048) per p
    gemm_mma_kernel<<<dim3(BN/128, 256/128, PP), 256, SMEM_G>>>(
        p_wqk_h, p_wqk_l, p_xd_h, p_xd_l, p_bqk, p_qk,
        256, BN, CC, (size_t)256*CC, (size_t)CC*BN, (size_t)256*BN, 256);

    attn_kernel<<<BB*PP, 256>>>();

    // y GEMM per (b,p): writes y_h/y_l directly
    y_mma_kernel<<<dim3(CC/128, BB, PP), 256, SMEM_G>>>();

    // AO GEMM: ao[c, bn] = vw[c,:] . y[:, bn] + vb   (M=2048, N=3072, K=2048) per p
    gemm_mma_kernel<<<dim3(BN/128, CC/128, PP), 256, SMEM_G>>>(
        p_vw_h, p_vw_l, p_y_h, p_y_l, v_b, p_ao,
        CC, BN, CC, (size_t)CC*CC, (size_t)CC*BN, (size_t)CC*BN, CC);

    gap_kernel<<<(PP*CC*BB)/8, 256>>>(pa_gamma);
    mlp_kernel<<<dim3(C4/128, PP), 256>>>(fc1_w, p_gap, fc1_b, p_h1, C4, CC, 0);
    mlp_kernel<<<dim3(CC/128, PP), 256>>>(fc2_w, p_h1, fc2_b, p_cw, CC, C4, 1);
    gate_kernel<<<1, 128>>>(gate_w1, gate_b1, gate_w2, gate_b2, modality);
    final_kernel<<<(BB*PP*CC)/8, 256>>>(x, pa_gamma, ca_gamma, out);
}

// round 7
// speedup vs baseline: 3.0282x; 1.4833x over previous
#include <cuda_runtime.h>
#include <cuda_bf16.h>
#include <math.h>
#include <stdint.h>

#define BB 32
#define CC 2048
#define HH 48
#define WW 24
#define PP 3
#define PHH 16
#define HD 8
#define WD 12
#define NN 96
#define ICC 128
#define C4 512
#define BN (BB*NN)   // 3072

// ---------------- scratch ----------------
__device__ __nv_bfloat16 g_xd[(size_t)PP*CC*BN];
__device__ __nv_bfloat16 g_wqk[(size_t)PP*256*CC];
__device__ __nv_bfloat16 g_vw[(size_t)PP*CC*CC];
__device__ __nv_bfloat16 g_at[(size_t)BB*PP*NN*NN + 64];
__device__ __nv_bfloat16 g_y[(size_t)PP*CC*BN];
__device__ __nv_bfloat16 g_ao[(size_t)PP*CC*BN];
__device__ float g_xmean[(size_t)PP*CC*BB];
__device__ float g_bqk[PP*256];
__device__ float g_qk[(size_t)PP*256*BN];
__device__ float g_gap[(size_t)PP*CC*BB];
__device__ float g_h1[(size_t)PP*C4*BB];
__device__ float g_cw[(size_t)PP*CC*BB];
__device__ float g_wgt[BB*PP];

// ---------------- PTX helpers ----------------
__device__ __forceinline__ uint32_t s2u(const void* p) {
    uint32_t a;
    asm("{ .reg .u64 t; cvta.to.shared.u64 t, %1; cvt.u32.u64 %0, t; }" : "=r"(a) : "l"(p));
    return a;
}
__device__ __forceinline__ void cpa16(uint32_t s, const void* g) {
    asm volatile("cp.async.ca.shared.global [%0], [%1], 16;" :: "r"(s), "l"(g));
}
__device__ __forceinline__ void cpa16z(uint32_t s, const void* g, int sz) {
    asm volatile("cp.async.ca.shared.global [%0], [%1], 16, %2;" :: "r"(s), "l"(g), "r"(sz));
}
#define CP_COMMIT() asm volatile("cp.async.commit_group;" ::: "memory")
#define CP_WAIT2()  asm volatile("cp.async.wait_group 2;" ::: "memory")

__device__ __forceinline__ void ldsm4(uint32_t* r, uint32_t a) {
    asm volatile("ldmatrix.sync.aligned.m8n8.x4.shared.b16 {%0,%1,%2,%3}, [%4];"
                 : "=r"(r[0]), "=r"(r[1]), "=r"(r[2]), "=r"(r[3]) : "r"(a));
}
__device__ __forceinline__ void ldsm4t(uint32_t* r, uint32_t a) {
    asm volatile("ldmatrix.sync.aligned.m8n8.x4.trans.shared.b16 {%0,%1,%2,%3}, [%4];"
                 : "=r"(r[0]), "=r"(r[1]), "=r"(r[2]), "=r"(r[3]) : "r"(a));
}
__device__ __forceinline__ void mma16816(float* c, const uint32_t* a, const uint32_t* b) {
    asm volatile("mma.sync.aligned.m16n8k16.row.col.f32.bf16.bf16.f32 "
                 "{%0,%1,%2,%3}, {%4,%5,%6,%7}, {%8,%9}, {%0,%1,%2,%3};"
                 : "+f"(c[0]), "+f"(c[1]), "+f"(c[2]), "+f"(c[3])
                 : "r"(a[0]), "r"(a[1]), "r"(a[2]), "r"(a[3]), "r"(b[0]), "r"(b[1]));
}

// SMEM geometry
#define A_TB 10240           // 128 x 40 bf16 (x2B)
#define B_TB 8704            // 32 x 136 bf16 (x2B)
#define GBUF (A_TB + B_TB)   // 18944
#define SMEM_G (3*GBUF)      // 56832  (3-stage pipeline)

// warp tile (32 x 64) over one k32 chunk
__device__ __forceinline__ void tile_compute(uint32_t sbase, int lane, int m_off, int n_off,
                                             float acc[2][8][4]) {
#pragma unroll
    for (int kh = 0; kh < 2; kh++) {
        uint32_t a[2][4];
#pragma unroll
        for (int tm = 0; tm < 2; tm++) {
            uint32_t off = ((m_off + tm*16 + (lane & 15))*40 + kh*16 + (lane >> 4)*8)*2;
            ldsm4(a[tm], sbase + off);
        }
#pragma unroll
        for (int g = 0; g < 4; g++) {
            uint32_t b4[4];
            uint32_t off = ((kh*16 + (lane & 15))*136 + n_off + g*16 + (lane >> 4)*8)*2;
            ldsm4t(b4, sbase + A_TB + off);
#pragma unroll
            for (int tm = 0; tm < 2; tm++) {
#pragma unroll
                for (int h2 = 0; h2 < 2; h2++) {
                    mma16816(acc[tm][g*2+h2], a[tm], &b4[h2*2]);
                }
            }
        }
    }
}

__device__ __forceinline__ void stage_load(uint32_t sbase,
    const __nv_bfloat16* A, const __nv_bfloat16* B,
    int kt, int K, int N, int tid)
{
#pragma unroll
    for (int i = 0; i < 2; i++) {
        int ch = tid + i*256;
        int r = ch >> 2, c8 = ch & 3;
        cpa16(sbase + (r*40 + c8*8)*2, A + (size_t)r*K + kt*32 + c8*8);
    }
#pragma unroll
    for (int i = 0; i < 2; i++) {
        int ch = tid + i*256;
        int r = ch >> 4, c8 = ch & 15;
        cpa16(sbase + A_TB + (r*136 + c8*8)*2, B + (size_t)(kt*32 + r)*N + c8*8);
    }
}

// ================= bf16 MMA GEMM: C = A(MxK) @ B(KxN) + bias =================
__global__ __launch_bounds__(256, 2) void gemm_mma_kernel(
    const __nv_bfloat16* __restrict__ A_, const __nv_bfloat16* __restrict__ B_,
    const float* __restrict__ bias_, void* __restrict__ C_,
    int M, int N, int K, size_t az, size_t bz, size_t cz, int biasz, int obf)
{
    extern __shared__ char smem[];
    uint32_t sb = s2u(smem);
    int tid = threadIdx.x, lane = tid & 31, wid = tid >> 5;
    int p = blockIdx.z;
    int bm = blockIdx.y * 128, bn = blockIdx.x * 128;
    const __nv_bfloat16* A = A_ + (size_t)p*az + (size_t)bm*K;
    const __nv_bfloat16* B = B_ + (size_t)p*bz + bn;
    const float* bias = bias_ + (size_t)p*biasz + bm;
    int m_off = (wid & 3)*32, n_off = (wid >> 2)*64;

    float acc[2][8][4];
#pragma unroll
    for (int a = 0; a < 2; a++)
#pragma unroll
        for (int b = 0; b < 8; b++)
#pragma unroll
            for (int c = 0; c < 4; c++) acc[a][b][c] = 0.f;

    int NK = K / 32;
    stage_load(sb, A, B, 0, K, N, tid);
    CP_COMMIT();
    if (NK > 1) stage_load(sb + GBUF, A, B, 1, K, N, tid);
    CP_COMMIT();
    if (NK > 2) stage_load(sb + 2*GBUF, A, B, 2, K, N, tid);
    CP_COMMIT();

    int bi = 0;
    for (int kt = 0; kt < NK; kt++) {
        CP_WAIT2();
        __syncthreads();
        uint32_t buf = sb + bi*GBUF;
        tile_compute(buf, lane, m_off, n_off, acc);
        __syncthreads();
        if (kt + 3 < NK) stage_load(buf, A, B, kt + 3, K, N, tid);
        CP_COMMIT();
        bi = (bi == 2) ? 0 : bi + 1;
    }

    int ri = lane >> 2, ci = (lane & 3)*2;
    if (!obf) {
        float* C = (float*)C_ + (size_t)p*cz + (size_t)bm*N + bn;
#pragma unroll
        for (int tm = 0; tm < 2; tm++) {
#pragma unroll
            for (int h = 0; h < 2; h++) {
                int row = m_off + tm*16 + ri + h*8;
                float bv = bias[row];
                float* crow = C + (size_t)row*N;
#pragma unroll
                for (int j = 0; j < 8; j++) {
                    float2 o;
                    o.x = acc[tm][j][h*2]   + bv;
                    o.y = acc[tm][j][h*2+1] + bv;
                    *(float2*)(crow + n_off + j*8 + ci) = o;
                }
            }
        }
    } else {
        __nv_bfloat16* C = (__nv_bfloat16*)C_ + (size_t)p*cz + (size_t)bm*N + bn;
#pragma unroll
        for (int tm = 0; tm < 2; tm++) {
#pragma unroll
            for (int h = 0; h < 2; h++) {
                int row = m_off + tm*16 + ri + h*8;
                float bv = bias[row];
                __nv_bfloat16* crow = C + (size_t)row*N;
#pragma unroll
                for (int j = 0; j < 8; j++) {
                    __nv_bfloat162 o;
                    o.x = __float2bfloat16(acc[tm][j][h*2]   + bv);
                    o.y = __float2bfloat16(acc[tm][j][h*2+1] + bv);
                    *(uint32_t*)(crow + n_off + j*8 + ci) = *(uint32_t*)&o;
                }
            }
        }
    }
}

// ================= y GEMM (per b,p): y[c,i] = sum_j xd[c,j] * aT[j,i]; bf16 out =================
__global__ __launch_bounds__(256, 2) void y_mma_kernel()
{
    extern __shared__ char smem[];
    uint32_t sb = s2u(smem);
    int tid = threadIdx.x, lane = tid & 31, wid = tid >> 5;
    int bm = blockIdx.x * 128;
    int b = blockIdx.y, p = blockIdx.z;
    const __nv_bfloat16* A = g_xd + (size_t)p*CC*BN + (size_t)bm*BN + b*NN;
    const __nv_bfloat16* Bm = g_at + (size_t)(b*PP + p)*NN*NN;
    int m_off = (wid & 3)*32, n_off = (wid >> 2)*64;

    float acc[2][8][4];
#pragma unroll
    for (int a = 0; a < 2; a++)
#pragma unroll
        for (int b2 = 0; b2 < 8; b2++)
#pragma unroll
            for (int c = 0; c < 4; c++) acc[a][b2][c] = 0.f;

    // K = 96 -> 3 chunks, all prefetched into the 3 stages
#pragma unroll
    for (int pre = 0; pre < 3; pre++) {
        uint32_t sbase = sb + pre*GBUF;
#pragma unroll
        for (int i = 0; i < 2; i++) {
            int ch = tid + i*256;
            int r = ch >> 2, c8 = ch & 3;
            cpa16(sbase + (r*40 + c8*8)*2, A + (size_t)r*BN + pre*32 + c8*8);
        }
#pragma unroll
        for (int i = 0; i < 2; i++) {
            int ch = tid + i*256;
            int r = ch >> 4, c8 = ch & 15;
            int sz = (c8 < 12) ? 16 : 0;
            size_t go = (size_t)(pre*32 + r)*NN + ((c8 < 12) ? c8*8 : 0);
            cpa16z(sbase + A_TB + (r*136 + c8*8)*2, Bm + go, sz);
        }
        CP_COMMIT();
    }
#pragma unroll
    for (int kt = 0; kt < 3; kt++) {
        CP_WAIT2();
        __syncthreads();
        tile_compute(sb + kt*GBUF, lane, m_off, n_off, acc);
        __syncthreads();
        CP_COMMIT();
    }

    int ri = lane >> 2, ci = (lane & 3)*2;
    __nv_bfloat16* y = g_y + (size_t)p*CC*BN + b*NN;
#pragma unroll
    for (int tm = 0; tm < 2; tm++) {
#pragma unroll
        for (int h = 0; h < 2; h++) {
            int row = bm + m_off + tm*16 + ri + h*8;
#pragma unroll
            for (int j = 0; j < 8; j++) {
                int col = n_off + j*8 + ci;
                if (col < NN) {
                    __nv_bfloat162 o;
                    o.x = __float2bfloat16(acc[tm][j][h*2]);
                    o.y = __float2bfloat16(acc[tm][j][h*2+1]);
                    *(uint32_t*)(y + (size_t)row*BN + col) = *(uint32_t*)&o;
                }
            }
        }
    }
}

// ================= K0: fold depthwise into QK weights/bias =================
__global__ void prep_wqk_kernel(const float* __restrict__ qw, const float* __restrict__ dwqw,
                                const float* __restrict__ dwqb, const float* __restrict__ qb,
                                const float* __restrict__ kw, const float* __restrict__ dwkw,
                                const float* __restrict__ dwkb, const float* __restrict__ kb)
{
    int bid = blockIdx.x;
    int p = bid / 256, m = bid % 256;
    const float *wsrc, *dww, *dwb; float bias0;
    if (m < 128) { wsrc = qw + ((size_t)p*128 + m)*CC; dww = dwqw + (size_t)p*CC; dwb = dwqb + (size_t)p*CC; bias0 = qb[p*128+m]; }
    else         { wsrc = kw + ((size_t)p*128 + (m-128))*CC; dww = dwkw + (size_t)p*CC; dwb = dwkb + (size_t)p*CC; bias0 = kb[p*128+(m-128)]; }
    __nv_bfloat16* wh = g_wqk + ((size_t)p*256 + m)*CC;
    float acc = 0.f;
    for (int c = threadIdx.x; c < CC; c += 256) {
        float w = wsrc[c];
        wh[c] = __float2bfloat16(w * dww[c]);
        acc += w * dwb[c];
    }
    __shared__ float red[256];
    red[threadIdx.x] = acc; __syncthreads();
    for (int s = 128; s > 0; s >>= 1) { if (threadIdx.x < s) red[threadIdx.x] += red[threadIdx.x+s]; __syncthreads(); }
    if (threadIdx.x == 0) g_bqk[p*256 + m] = bias0 + red[0];
}

// ================= K1: downsample + mean (bf16 out) =================
__global__ __launch_bounds__(256) void downsample_kernel(const float* __restrict__ x)
{
    int gw = blockIdx.x * 8 + (threadIdx.x >> 5);
    int lane = threadIdx.x & 31;
    int wl = threadIdx.x >> 5;
    int b = gw / (PP*CC);
    int rem = gw % (PP*CC);
    int p = rem / CC;
    int c = rem % CC;
    const float* src = x + ((((size_t)b*CC + c)*HH) + (size_t)p*PHH) * WW;
    __shared__ float s[8][384];
    float* sw = s[wl];
    float sum = 0.f;
#pragma unroll
    for (int t = 0; t < 12; t++) { float v = src[lane + t*32]; sw[lane + t*32] = v; sum += v; }
#pragma unroll
    for (int o = 16; o > 0; o >>= 1) sum += __shfl_xor_sync(0xffffffffu, sum, o);
    __syncwarp();
    size_t dbase = ((size_t)p*CC + c)*BN + b*NN;
#pragma unroll
    for (int t = 0; t < 3; t++) {
        int n = lane + t*32;
        int hd = n / WD, wd = n % WD;
        int base = (hd*2)*WW + wd*2;
        float v = 0.25f * (sw[base] + sw[base+1] + sw[base+WW] + sw[base+WW+1]);
        g_xd[dbase + n] = __float2bfloat16(v);
    }
    if (lane == 0) g_xmean[((size_t)p*CC + c)*BB + b] = sum * (1.0f/384.0f);
}

// ================= conv vw fp32 -> bf16 =================
__global__ __launch_bounds__(256) void conv_vw_kernel(const float* __restrict__ vw)
{
    size_t i = ((size_t)blockIdx.x*256 + threadIdx.x)*4;
    float4 v = *(const float4*)(vw + i);
    __nv_bfloat162 a; a.x = __float2bfloat16(v.x); a.y = __float2bfloat16(v.y);
    __nv_bfloat162 b; b.x = __float2bfloat16(v.z); b.y = __float2bfloat16(v.w);
    uint2 o = { *(uint32_t*)&a, *(uint32_t*)&b };
    *(uint2*)(g_vw + i) = o;
}

// ================= K3a: energy + softmax; write transposed attn bf16 =================
__global__ __launch_bounds__(256) void attn_kernel()
{
    int b = blockIdx.x / PP, p = blockIdx.x % PP;
    __shared__ float qs[8][96], ks[8][96];
    __shared__ float es[96][97];
    __shared__ float rinv[96];
    int tid = threadIdx.x;
    int tx = tid & 15, ty = tid >> 4;
    int n0 = tx*6, m0 = ty*6;
    float acc[6][6];
#pragma unroll
    for (int u = 0; u < 6; u++)
#pragma unroll
        for (int v = 0; v < 6; v++) acc[u][v] = 0.f;

    const float* qbase = g_qk + (size_t)p*256*BN + (size_t)b*NN;

    for (int i0 = 0; i0 < ICC; i0 += 8) {
        for (int t = tid; t < 8*96; t += 256) {
            int r = t / 96, col = t % 96;
            qs[r][col] = qbase[(size_t)(i0 + r)*BN + col];
            ks[r][col] = qbase[(size_t)(128 + i0 + r)*BN + col];
        }
        __syncthreads();
#pragma unroll
        for (int ii = 0; ii < 8; ii++) {
            float a[6], bb[6];
#pragma unroll
            for (int u = 0; u < 6; u++) a[u] = qs[ii][n0+u];
#pragma unroll
            for (int v = 0; v < 6; v++) bb[v] = ks[ii][m0+v];
#pragma unroll
            for (int u = 0; u < 6; u++)
#pragma unroll
                for (int v = 0; v < 6; v++) acc[u][v] = fmaf(a[u], bb[v], acc[u][v]);
        }
        __syncthreads();
    }
#pragma unroll
    for (int u = 0; u < 6; u++)
#pragma unroll
        for (int v = 0; v < 6; v++) es[n0+u][m0+v] = acc[u][v];
    __syncthreads();

    if (tid < 96) {
        float mx = -1e30f;
        for (int m = 0; m < 96; m++) mx = fmaxf(mx, es[tid][m]);
        float s = 0.f;
        for (int m = 0; m < 96; m++) { float e = expf(es[tid][m] - mx); es[tid][m] = e; s += e; }
        rinv[tid] = 1.0f / s;
    }
    __syncthreads();
    __nv_bfloat16* th = g_at + (size_t)(b*PP + p)*NN*NN;
    for (int t = tid; t < 96*96; t += 256) {
        int i = t / 96, j = t % 96;
        th[j*96 + i] = __float2bfloat16(es[i][j] * rinv[i]);
    }
}

// ================= K4: gap =================
__global__ __launch_bounds__(256) void gap_kernel(const float* __restrict__ pa_gamma)
{
    int idx = blockIdx.x * 8 + (threadIdx.x >> 5);
    int lane = threadIdx.x & 31;
    int pc = idx / BB;
    int p = pc / CC;
    const __nv_bfloat16* src = g_ao + (size_t)idx*NN;
    float s = 0.f;
#pragma unroll
    for (int t = 0; t < 3; t++) s += __bfloat162float(src[lane + t*32]);
#pragma unroll
    for (int o = 16; o > 0; o >>= 1) s += __shfl_xor_sync(0xffffffffu, s, o);
    if (lane == 0) g_gap[idx] = pa_gamma[p] * (s * (1.0f/96.0f)) + g_xmean[idx];
}

// ================= K5: batched MLP =================
__global__ __launch_bounds__(256) void mlp_kernel(const float* __restrict__ Ag, const float* __restrict__ Xg,
                                                  const float* __restrict__ biasg, float* __restrict__ outg,
                                                  int M, int K, int act)
{
    int p = blockIdx.y;
    const float* A = Ag + (size_t)p*M*K;
    const float* X = Xg + (size_t)p*K*BB;
    const float* bias = biasg + (size_t)p*M;
    float* out = outg + (size_t)p*M*BB;
    int m0 = blockIdx.x * 128;
    int tid = threadIdx.x;
    int bb = tid & 31, g = tid >> 5;
    __shared__ float xsm[32][33];
    __shared__ float wsm[128][33];
    float acc[16];
#pragma unroll
    for (int r = 0; r < 16; r++) acc[r] = 0.f;

    for (int k0 = 0; k0 < K; k0 += 32) {
        for (int t = tid; t < 32*32; t += 256) { int kk = t >> 5, b2 = t & 31; xsm[kk][b2] = X[(size_t)(k0+kk)*BB + b2]; }
        for (int t = tid; t < 128*32; t += 256) { int r = t >> 5, kk = t & 31; wsm[r][kk] = A[(size_t)(m0+r)*K + k0 + kk]; }
        __syncthreads();
#pragma unroll
        for (int kk = 0; kk < 32; kk++) {
            float xv = xsm[kk][bb];
#pragma unroll
            for (int r = 0; r < 16; r++) acc[r] = fmaf(wsm[g*16+r][kk], xv, acc[r]);
        }
        __syncthreads();
    }
#pragma unroll
    for (int r = 0; r < 16; r++) {
        int m = m0 + g*16 + r;
        float v = acc[r] + bias[m];
        v = (act == 0) ? fmaxf(v, 0.f) : 1.f/(1.f + expf(-v));
        out[(size_t)m*BB + bb] = v;
    }
}

// ================= K6: modality gate =================
__global__ void gate_kernel(const float* __restrict__ w1, const float* __restrict__ b1,
                            const float* __restrict__ w2, const float* __restrict__ b2,
                            const int* __restrict__ modality)
{
    int t = threadIdx.x;
    if (t >= BB*PP) return;
    int b = t / PP, p = t % PP;
    float mf = (float)modality[b];
    float s = b2[p];
#pragma unroll
    for (int j = 0; j < 12; j++) {
        float g1 = fmaxf(mf * w1[j] + b1[j], 0.f);
        s += g1 * w2[p*12 + j];
    }
    g_wgt[t] = 1.f/(1.f + expf(-s));
}

// ================= K7: fused upsample + residual + gates =================
__global__ __launch_bounds__(256) void final_kernel(const float* __restrict__ x,
                                                    const float* __restrict__ pa_gamma,
                                                    const float* __restrict__ ca_gamma,
                                                    float* __restrict__ out)
{
    int gw = blockIdx.x * 8 + (threadIdx.x >> 5);
    int lane = threadIdx.x & 31;
    int wl = threadIdx.x >> 5;
    int b = gw / (PP*CC);
    int rem = gw % (PP*CC);
    int p = rem / CC;
    int c = rem % CC;
    __shared__ float aos[8][96];
    const __nv_bfloat16* asrc = g_ao + (((size_t)p*CC + c)*BB + b)*NN;
#pragma unroll
    for (int t = 0; t < 3; t++) aos[wl][lane + t*32] = __bfloat162float(asrc[lane + t*32]);
    __syncwarp();

    float wgt = g_wgt[b*PP + p];
    float cwv = g_cw[((size_t)p*CC + c)*BB + b];
    float fac = (1.f + ca_gamma[p]*cwv) * wgt;
    float gamma = pa_gamma[p];
    size_t base = (((size_t)b*CC + c)*HH + (size_t)p*PHH) * WW;

#pragma unroll
    for (int t = 0; t < 12; t++) {
        int idx = lane + t*32;
        int ph = idx / WW, w = idx % WW;
        int ih = (ph - 1) >> 1;
        float th = (ph & 1) ? 0.25f : 0.75f;
        int r0 = ih < 0 ? 0 : ih;
        int r1 = (ih + 1 > HD-1) ? (HD-1) : (ih + 1);
        int iw = (w - 1) >> 1;
        float tw = (w & 1) ? 0.25f : 0.75f;
        int q0 = iw < 0 ? 0 : iw;
        int q1 = (iw + 1 > WD-1) ? (WD-1) : (iw + 1);
        float up = (1.f - th)*((1.f - tw)*aos[wl][r0*WD+q0] + tw*aos[wl][r0*WD+q1])
                 +        th *((1.f - tw)*aos[wl][r1*WD+q0] + tw*aos[wl][r1*WD+q1]);
        float xv = x[base + idx];
        float pa = gamma*up + xv;
        out[base + idx] = xv*(1.f - wgt) + pa*fac;
    }
}

// ================= host =================
extern "C" void kernel_launch(void* const* d_in, const int* in_sizes, int n_in,
                              void* d_out, int out_size)
{
    const float* x        = (const float*)d_in[0];
    const float* dwq_w    = (const float*)d_in[1];
    const float* dwq_b    = (const float*)d_in[2];
    const float* q_w      = (const float*)d_in[3];
    const float* q_b      = (const float*)d_in[4];
    const float* dwk_w    = (const float*)d_in[5];
    const float* dwk_b    = (const float*)d_in[6];
    const float* k_w      = (const float*)d_in[7];
    const float* k_b      = (const float*)d_in[8];
    const float* v_w      = (const float*)d_in[9];
    const float* v_b      = (const float*)d_in[10];
    const float* pa_gamma = (const float*)d_in[11];
    const float* fc1_w    = (const float*)d_in[12];
    const float* fc1_b    = (const float*)d_in[13];
    const float* fc2_w    = (const float*)d_in[14];
    const float* fc2_b    = (const float*)d_in[15];
    const float* ca_gamma = (const float*)d_in[16];
    const float* gate_w1  = (const float*)d_in[17];
    const float* gate_b1  = (const float*)d_in[18];
    const float* gate_w2  = (const float*)d_in[19];
    const float* gate_b2  = (const float*)d_in[20];
    const int*   modality = (const int*)d_in[21];
    float* out = (float*)d_out;

    __nv_bfloat16 *p_wqk, *p_xd, *p_vw, *p_y, *p_ao;
    float *p_bqk, *p_qk, *p_gap, *p_h1, *p_cw;
    cudaGetSymbolAddress((void**)&p_wqk, g_wqk);
    cudaGetSymbolAddress((void**)&p_xd,  g_xd);
    cudaGetSymbolAddress((void**)&p_vw,  g_vw);
    cudaGetSymbolAddress((void**)&p_y,   g_y);
    cudaGetSymbolAddress((void**)&p_ao,  g_ao);
    cudaGetSymbolAddress((void**)&p_bqk, g_bqk);
    cudaGetSymbolAddress((void**)&p_qk,  g_qk);
    cudaGetSymbolAddress((void**)&p_gap, g_gap);
    cudaGetSymbolAddress((void**)&p_h1,  g_h1);
    cudaGetSymbolAddress((void**)&p_cw,  g_cw);

    static bool attr_done = false;
    if (!attr_done) {
        cudaFuncSetAttribute(gemm_mma_kernel, cudaFuncAttributeMaxDynamicSharedMemorySize, SMEM_G);
        cudaFuncSetAttribute(y_mma_kernel,    cudaFuncAttributeMaxDynamicSharedMemorySize, SMEM_G);
        attr_done = true;
    }

    prep_wqk_kernel<<<PP*256, 256>>>(q_w, dwq_w, dwq_b, q_b, k_w, dwk_w, dwk_b, k_b);
    downsample_kernel<<<(BB*PP*CC)/8, 256>>>(x);
    conv_vw_kernel<<<(PP*CC*CC)/(256*4), 256>>>(v_w);

    // QK GEMM: qk[m, bn] = wqk[m,:] . xd[:, bn] + bqk   (fp32 out)
    gemm_mma_kernel<<<dim3(BN/128, 256/128, PP), 256, SMEM_G>>>(
        p_wqk, p_xd, p_bqk, p_qk,
        256, BN, CC, (size_t)256*CC, (size_t)CC*BN, (size_t)256*BN, 256, 0);

    attn_kernel<<<BB*PP, 256>>>();

    // y GEMM per (b,p): bf16 out
    y_mma_kernel<<<dim3(CC/128, BB, PP), 256, SMEM_G>>>();

    // AO GEMM: ao[c, bn] = vw[c,:] . y[:, bn] + vb   (bf16 out)
    gemm_mma_kernel<<<dim3(BN/128, CC/128, PP), 256, SMEM_G>>>(
        p_vw, p_y, v_b, p_ao,
        CC, BN, CC, (size_t)CC*CC, (size_t)CC*BN, (size_t)CC*BN, CC, 1);

    gap_kernel<<<(PP*CC*BB)/8, 256>>>(pa_gamma);
    mlp_kernel<<<dim3(C4/128, PP), 256>>>(fc1_w, p_gap, fc1_b, p_h1, C4, CC, 0);
    mlp_kernel<<<dim3(CC/128, PP), 256>>>(fc2_w, p_h1, fc2_b, p_cw, CC, C4, 1);
    gate_kernel<<<1, 128>>>(gate_w1, gate_b1, gate_w2, gate_b2, modality);
    final_kernel<<<(BB*PP*CC)/8, 256>>>(x, pa_gamma, ca_gamma, out);
}